// round 7
// baseline (speedup 1.0000x reference)
#include <cuda_runtime.h>
#include <cuda_fp16.h>

// ---------------------------------------------------------------------------
// LocalWLNet round 6: flat kernels with stats fused via shared atomics,
// interleaved AB output, merged dual conv2 gather. 14 launches.
// ---------------------------------------------------------------------------

#define MAXN   100000
#define MAXP   1000000
#define MAXE1  3200000
#define MAXE2  4000000
#define EPSV   1e-5f

__device__ float g_node0[MAXN * 32];
__device__ float g_node1[MAXN * 32];
__device__ float g_node2[MAXN * 32];
__device__ uint4 g_pairHa[MAXP * 3];   // fp16: 24 halfs = 3 x uint4 per row
__device__ uint4 g_pairHb[MAXP * 3];
__device__ float g_pairAB[(size_t)MAXP * 48];  // interleaved [A24|B24]

__device__ int   g_cnt1[MAXN],  g_off1[MAXN];
__device__ int   g_cnt2f[MAXP], g_off2f[MAXP];
__device__ int   g_cnt2r[MAXP], g_off2r[MAXP];
__device__ float g_dinv1[MAXN], g_dinv2f[MAXP], g_dinv2r[MAXP];
__device__ int   g_e1[MAXE1];
__device__ int   g_e2f[MAXE2];
__device__ int   g_e2r[MAXE2];
__device__ int   g_aux[3072];
__device__ float g_statsf[5 * 64];   // per slot: [0:32) sum, [32:64) sumsq

static inline int GRID(long long n, int b) { return (int)((n + b - 1) / b); }

__device__ inline unsigned pack2(float a, float b) {
    __half2 h = __floats2half2_rn(a, b);
    return *reinterpret_cast<unsigned*>(&h);
}
__device__ inline float2 unpack2(unsigned u) {
    __half2 h = *reinterpret_cast<__half2*>(&u);
    return __half22float2(h);
}

// ---------------- zero accumulators ----------------
__global__ void k_zero(int* c1, int* c2f, int* c2r, float* st, int N, int P) {
    int i = blockIdx.x * blockDim.x + threadIdx.x;
    if (i < P) { c2f[i] = 0; c2r[i] = 0; }
    if (i < N) c1[i] = 0;
    if (i < 5 * 64) st[i] = 0.0f;
}

// ---------------- all three degree counts, one pass ----------------
__global__ void k_cnt_all(const int* __restrict__ edge1, int E1,
                          const int* __restrict__ ei2, int E2,
                          int* __restrict__ c1, int* __restrict__ c2f, int* __restrict__ c2r) {
    int i = blockIdx.x * blockDim.x + threadIdx.x;
    if (i < E1) atomicAdd(&c1[edge1[E1 + i]], 1);
    if (i < E2) {
        atomicAdd(&c2f[ei2[E2 + i]], 1);  // fwd dst = ei2[1]
        atomicAdd(&c2r[ei2[i]], 1);       // rev dst = ei2[0]
    }
}

// ---------------- sectioned exclusive scan ----------------
__global__ void k_scan1_all(const int* __restrict__ c1, int N,
                            const int* __restrict__ c2f, const int* __restrict__ c2r, int P,
                            int* __restrict__ o1, int* __restrict__ o2f, int* __restrict__ o2r,
                            int* __restrict__ aux, int nb1, int nb2) {
    const int* src; int* dst; int n, lb, ao;
    int b = blockIdx.x;
    if (b < nb1)            { src = c1;  dst = o1;  n = N; lb = b;             ao = 0; }
    else if (b < nb1 + nb2) { src = c2f; dst = o2f; n = P; lb = b - nb1;       ao = 1024; }
    else                    { src = c2r; dst = o2r; n = P; lb = b - nb1 - nb2; ao = 2048; }
    __shared__ int sh[1024];
    int i = lb * 1024 + threadIdx.x;
    int v = (i < n) ? src[i] : 0;
    sh[threadIdx.x] = v;
    __syncthreads();
    for (int o = 1; o < 1024; o <<= 1) {
        int t = (threadIdx.x >= o) ? sh[threadIdx.x - o] : 0;
        __syncthreads();
        sh[threadIdx.x] += t;
        __syncthreads();
    }
    if (i < n) dst[i] = sh[threadIdx.x] - v;  // exclusive within block
    if (threadIdx.x == 1023) aux[ao + lb] = sh[1023];
}

__global__ void k_scan2_all(int* __restrict__ aux, int nb1, int nb2) {
    int ao = blockIdx.x * 1024;
    int nb = (blockIdx.x == 0) ? nb1 : nb2;
    __shared__ int sh[1024];
    int v = (threadIdx.x < nb) ? aux[ao + threadIdx.x] : 0;
    sh[threadIdx.x] = v;
    __syncthreads();
    for (int o = 1; o < 1024; o <<= 1) {
        int t = (threadIdx.x >= o) ? sh[threadIdx.x - o] : 0;
        __syncthreads();
        sh[threadIdx.x] += t;
        __syncthreads();
    }
    if (threadIdx.x < nb) aux[ao + threadIdx.x] = sh[threadIdx.x] - v;  // exclusive
}

// scan3 + dinv
__global__ void k_scan3_all(int* __restrict__ o1, const int* __restrict__ c1,
                            float* __restrict__ dv1, int N,
                            int* __restrict__ o2f, const int* __restrict__ c2f,
                            float* __restrict__ dv2f,
                            int* __restrict__ o2r, const int* __restrict__ c2r,
                            float* __restrict__ dv2r, int P,
                            const int* __restrict__ aux, int nbe1, int nbe2) {
    int b = blockIdx.x;
    int* off; const int* cnt; float* dv; int n, lb, ao;
    if (b < nbe1)             { off = o1;  cnt = c1;  dv = dv1;  n = N; lb = b;               ao = 0; }
    else if (b < nbe1 + nbe2) { off = o2f; cnt = c2f; dv = dv2f; n = P; lb = b - nbe1;        ao = 1024; }
    else                      { off = o2r; cnt = c2r; dv = dv2r; n = P; lb = b - nbe1 - nbe2; ao = 2048; }
    int i = lb * 256 + threadIdx.x;
    if (i < n) {
        off[i] += aux[ao + (i >> 10)];
        dv[i] = rsqrtf((float)cnt[i] + 1.0f);
    }
}

// ---------------- fill all CSRs (off doubles as cursor) ----------------
__global__ void k_fill_all(const int* __restrict__ edge1, int E1,
                           const int* __restrict__ ei2, int E2,
                           int* __restrict__ o1, int* __restrict__ o2f, int* __restrict__ o2r,
                           int* __restrict__ e1, int* __restrict__ e2f, int* __restrict__ e2r) {
    int i = blockIdx.x * blockDim.x + threadIdx.x;
    if (i < E1) {
        int s = edge1[i], d = edge1[E1 + i];
        e1[atomicAdd(&o1[d], 1)] = s;
    }
    if (i < E2) {
        int s = ei2[i], d = ei2[E2 + i];
        e2f[atomicAdd(&o2f[d], 1)] = s;
        e2r[atomicAdd(&o2r[s], 1)] = d;
    }
}

// ---------------- embedding gather + GN0 stats (flat) ----------------
__global__ void k_embed_stats(const int* __restrict__ ids, const float* __restrict__ emb,
                              float* __restrict__ out, int n, float* __restrict__ st) {
    __shared__ float shS[32], shQ[32];
    if (threadIdx.x < 32) { shS[threadIdx.x] = 0.0f; shQ[threadIdx.x] = 0.0f; }
    __syncthreads();
    int t = blockIdx.x * blockDim.x + threadIdx.x;
    int r = t >> 3, g = t & 7;
    if (r < n) {
        float4 v = *(const float4*)(emb + (size_t)ids[r] * 32 + g * 4);
        *(float4*)(out + (size_t)r * 32 + g * 4) = v;
        atomicAdd(&shS[g * 4 + 0], v.x); atomicAdd(&shS[g * 4 + 1], v.y);
        atomicAdd(&shS[g * 4 + 2], v.z); atomicAdd(&shS[g * 4 + 3], v.w);
        atomicAdd(&shQ[g * 4 + 0], v.x * v.x); atomicAdd(&shQ[g * 4 + 1], v.y * v.y);
        atomicAdd(&shQ[g * 4 + 2], v.z * v.z); atomicAdd(&shQ[g * 4 + 3], v.w * v.w);
    }
    __syncthreads();
    if (threadIdx.x < 32) {
        atomicAdd(&st[threadIdx.x], shS[threadIdx.x]);
        atomicAdd(&st[32 + threadIdx.x], shQ[threadIdx.x]);
    }
}

// ---------------- h' = dinv * (norm(x) @ W) ----------------
template <int CIN, int COUT, int RELU>
__global__ void k_mm(const float* __restrict__ x, const float* __restrict__ W,
                     const float* __restrict__ dinv, float* __restrict__ h, int n,
                     const float* __restrict__ st, const float* __restrict__ gw,
                     const float* __restrict__ gb, const float* __restrict__ ga) {
    __shared__ float Ws[CIN * COUT];
    __shared__ float S[CIN], T[CIN];
    for (int t = threadIdx.x; t < CIN * COUT; t += blockDim.x) Ws[t] = W[t];
    if (threadIdx.x < CIN) {
        int c = threadIdx.x;
        double av = (double)ga[c];
        double m = (double)st[c] / n;
        double var = (double)st[32 + c] / n - m * m * av * (2.0 - av);
        float s = gw[c] * rsqrtf((float)var + EPSV);
        S[c] = s;
        T[c] = gb[c] - (float)((double)s * av * m);
    }
    __syncthreads();
    int i = blockIdx.x * blockDim.x + threadIdx.x;
    if (i >= n) return;
    float acc[COUT];
#pragma unroll
    for (int j = 0; j < COUT; j++) acc[j] = 0.0f;
    const float* xr = x + (size_t)i * CIN;
#pragma unroll
    for (int k = 0; k < CIN; k++) {
        float xv = S[k] * xr[k] + T[k];
        if (RELU) xv = fmaxf(xv, 0.0f);
#pragma unroll
        for (int j = 0; j < COUT; j++) acc[j] += xv * Ws[k * COUT + j];
    }
    float dv = dinv[i];
    float* hr = h + (size_t)i * COUT;
#pragma unroll
    for (int j = 0; j < COUT; j++) hr[j] = dv * acc[j];
}

// ---------------- fp32 CSR gather (flat) + fused stats ----------------
template <int C>
__global__ void k_gather_st(const int* __restrict__ off, const int* __restrict__ edge,
                            const float* __restrict__ dinv, const float4* __restrict__ h4,
                            const float* __restrict__ bias, float4* __restrict__ out, int n,
                            float* __restrict__ st) {
    constexpr int G = C / 4;
    __shared__ float shS[C], shQ[C];
    if (threadIdx.x < C) { shS[threadIdx.x] = 0.0f; shQ[threadIdx.x] = 0.0f; }
    __syncthreads();
    long long t = (long long)blockIdx.x * blockDim.x + threadIdx.x;
    int node = (int)(t / G);
    int g = (int)(t % G);
    if (node < n) {
        float4 sum = h4[(size_t)node * G + g];
        int beg = node ? off[node - 1] : 0;  // off[d] = end after fill
        int end = off[node];
        for (int j = beg; j < end; j++) {
            float4 v = h4[(size_t)edge[j] * G + g];
            sum.x += v.x; sum.y += v.y; sum.z += v.z; sum.w += v.w;
        }
        float dv = dinv[node];
        float4 acc;
        acc.x = dv * sum.x + bias[g * 4 + 0];
        acc.y = dv * sum.y + bias[g * 4 + 1];
        acc.z = dv * sum.z + bias[g * 4 + 2];
        acc.w = dv * sum.w + bias[g * 4 + 3];
        out[(size_t)node * G + g] = acc;
        atomicAdd(&shS[g * 4 + 0], acc.x); atomicAdd(&shS[g * 4 + 1], acc.y);
        atomicAdd(&shS[g * 4 + 2], acc.z); atomicAdd(&shS[g * 4 + 3], acc.w);
        atomicAdd(&shQ[g * 4 + 0], acc.x * acc.x); atomicAdd(&shQ[g * 4 + 1], acc.y * acc.y);
        atomicAdd(&shQ[g * 4 + 2], acc.z * acc.z); atomicAdd(&shQ[g * 4 + 3], acc.w * acc.w);
    }
    __syncthreads();
    if (threadIdx.x < C) {
        atomicAdd(&st[threadIdx.x], shS[threadIdx.x]);
        atomicAdd(&st[32 + threadIdx.x], shQ[threadIdx.x]);
    }
}

// ---------------- pair: xp = norm(x[a])*norm(x[b]); dual GEMM; fp16 out ----
__global__ void k_pair_mm(const int* __restrict__ pos, const float* __restrict__ xn,
                          int nNode, const float* __restrict__ st,
                          const float* __restrict__ gw, const float* __restrict__ gb,
                          const float* __restrict__ ga, const float* __restrict__ W1,
                          const float* __restrict__ W2, const float* __restrict__ dvf,
                          const float* __restrict__ dvr, uint4* __restrict__ ha,
                          uint4* __restrict__ hb, int P) {
    __shared__ float Ws1[24 * 24], Ws2[24 * 24], S[24], T[24];
    for (int t = threadIdx.x; t < 24 * 24; t += blockDim.x) {
        Ws1[t] = W1[t];
        Ws2[t] = W2[t];
    }
    if (threadIdx.x < 24) {
        int c = threadIdx.x;
        double av = (double)ga[c];
        double m = (double)st[c] / nNode;
        double var = (double)st[32 + c] / nNode - m * m * av * (2.0 - av);
        float s = gw[c] * rsqrtf((float)var + EPSV);
        S[c] = s;
        T[c] = gb[c] - (float)((double)s * av * m);
    }
    __syncthreads();
    int p = blockIdx.x * blockDim.x + threadIdx.x;
    if (p >= P) return;
    int ia = pos[2 * p], ib = pos[2 * p + 1];
    const float4* x4 = (const float4*)xn;
    float x[24];
#pragma unroll
    for (int q = 0; q < 6; q++) {
        float4 va = x4[(size_t)ia * 6 + q];
        float4 vb = x4[(size_t)ib * 6 + q];
        int c = q * 4;
        x[c + 0] = (S[c + 0] * va.x + T[c + 0]) * (S[c + 0] * vb.x + T[c + 0]);
        x[c + 1] = (S[c + 1] * va.y + T[c + 1]) * (S[c + 1] * vb.y + T[c + 1]);
        x[c + 2] = (S[c + 2] * va.z + T[c + 2]) * (S[c + 2] * vb.z + T[c + 2]);
        x[c + 3] = (S[c + 3] * va.w + T[c + 3]) * (S[c + 3] * vb.w + T[c + 3]);
    }
    float a1[24], a2[24];
#pragma unroll
    for (int j = 0; j < 24; j++) { a1[j] = 0.0f; a2[j] = 0.0f; }
#pragma unroll
    for (int k = 0; k < 24; k++) {
        float xv = x[k];
#pragma unroll
        for (int j = 0; j < 24; j++) {
            a1[j] += xv * Ws1[k * 24 + j];
            a2[j] += xv * Ws2[k * 24 + j];
        }
    }
    float df = dvf[p], dr = dvr[p];
    uint4 u;
    u.x = pack2(df * a1[0], df * a1[1]);   u.y = pack2(df * a1[2], df * a1[3]);
    u.z = pack2(df * a1[4], df * a1[5]);   u.w = pack2(df * a1[6], df * a1[7]);
    ha[(size_t)p * 3 + 0] = u;
    u.x = pack2(df * a1[8], df * a1[9]);   u.y = pack2(df * a1[10], df * a1[11]);
    u.z = pack2(df * a1[12], df * a1[13]); u.w = pack2(df * a1[14], df * a1[15]);
    ha[(size_t)p * 3 + 1] = u;
    u.x = pack2(df * a1[16], df * a1[17]); u.y = pack2(df * a1[18], df * a1[19]);
    u.z = pack2(df * a1[20], df * a1[21]); u.w = pack2(df * a1[22], df * a1[23]);
    ha[(size_t)p * 3 + 2] = u;
    u.x = pack2(dr * a2[0], dr * a2[1]);   u.y = pack2(dr * a2[2], dr * a2[3]);
    u.z = pack2(dr * a2[4], dr * a2[5]);   u.w = pack2(dr * a2[6], dr * a2[7]);
    hb[(size_t)p * 3 + 0] = u;
    u.x = pack2(dr * a2[8], dr * a2[9]);   u.y = pack2(dr * a2[10], dr * a2[11]);
    u.z = pack2(dr * a2[12], dr * a2[13]); u.w = pack2(dr * a2[14], dr * a2[15]);
    hb[(size_t)p * 3 + 1] = u;
    u.x = pack2(dr * a2[16], dr * a2[17]); u.y = pack2(dr * a2[18], dr * a2[19]);
    u.z = pack2(dr * a2[20], dr * a2[21]); u.w = pack2(dr * a2[22], dr * a2[23]);
    hb[(size_t)p * 3 + 2] = u;
}

// ---------------- dual fp16 gather (flat, fwd|rev halves) + fused stats ----
// Writes interleaved AB rows: fwd -> [node*48 + g*8), rev -> [node*48+24 + g*8)
__global__ void k_gather_h2(const int* __restrict__ offF, const int* __restrict__ eF,
                            const float* __restrict__ dvF, const uint4* __restrict__ hA,
                            const float* __restrict__ biasA,
                            const int* __restrict__ offR, const int* __restrict__ eR,
                            const float* __restrict__ dvR, const uint4* __restrict__ hB,
                            const float* __restrict__ biasB,
                            float* __restrict__ outAB, int n,
                            float* __restrict__ stA, float* __restrict__ stB) {
    __shared__ float shS[24], shQ[24];
    if (threadIdx.x < 24) { shS[threadIdx.x] = 0.0f; shQ[threadIdx.x] = 0.0f; }
    __syncthreads();
    long long half = (long long)n * 3;
    long long t = (long long)blockIdx.x * blockDim.x + threadIdx.x;
    bool rev = (t >= half);
    long long lt = rev ? t - half : t;
    int node = (int)(lt / 3);
    int g = (int)(lt % 3);
    bool valid = node < n;
    if (valid) {
        const int* off = rev ? offR : offF;
        const int* edge = rev ? eR : eF;
        const uint4* h = rev ? hB : hA;
        const float* bias = rev ? biasB : biasA;
        const float* dinv = rev ? dvR : dvF;
        float f[8];
        {
            uint4 u = h[(size_t)node * 3 + g];
            float2 a = unpack2(u.x), b = unpack2(u.y), c = unpack2(u.z), d = unpack2(u.w);
            f[0] = a.x; f[1] = a.y; f[2] = b.x; f[3] = b.y;
            f[4] = c.x; f[5] = c.y; f[6] = d.x; f[7] = d.y;
        }
        int beg = node ? off[node - 1] : 0;
        int end = off[node];
        for (int j = beg; j < end; j++) {
            uint4 u = h[(size_t)edge[j] * 3 + g];
            float2 a = unpack2(u.x), b = unpack2(u.y), c = unpack2(u.z), d = unpack2(u.w);
            f[0] += a.x; f[1] += a.y; f[2] += b.x; f[3] += b.y;
            f[4] += c.x; f[5] += c.y; f[6] += d.x; f[7] += d.y;
        }
        float dv = dinv[node];
        float o[8];
#pragma unroll
        for (int k = 0; k < 8; k++) o[k] = dv * f[k] + bias[g * 8 + k];
        float* base = outAB + (size_t)node * 48 + (rev ? 24 : 0) + g * 8;
        float4 w0, w1;
        w0.x = o[0]; w0.y = o[1]; w0.z = o[2]; w0.w = o[3];
        w1.x = o[4]; w1.y = o[5]; w1.z = o[6]; w1.w = o[7];
        ((float4*)base)[0] = w0;
        ((float4*)base)[1] = w1;
#pragma unroll
        for (int k = 0; k < 8; k++) {
            atomicAdd(&shS[g * 8 + k], o[k]);
            atomicAdd(&shQ[g * 8 + k], o[k] * o[k]);
        }
    }
    __syncthreads();
    // one block handles only fwd or rev threads except possibly one boundary
    // block; accumulate to the right stats slot per-thread group.
    if (threadIdx.x < 24) {
        // determine this block's halves: check both possibilities cheaply by
        // splitting the block reduction per warp-group is complex; instead each
        // valid thread contributed to shS which is shared between halves only
        // in the single boundary block. To stay exact, route via the first
        // thread's half when uniform; boundary block handled by atomics below.
        ;
    }
    // Exact routing: recompute from this thread's global slot whether the
    // corresponding column belongs to fwd or rev is not possible (mixed block).
    // Use per-half shared arrays instead.
    __syncthreads();
}

// The mixed-boundary-block issue above makes single shS ambiguous; use a
// corrected version with separate fwd/rev shared arrays.
__global__ void k_gather_h2x(const int* __restrict__ offF, const int* __restrict__ eF,
                             const float* __restrict__ dvF, const uint4* __restrict__ hA,
                             const float* __restrict__ biasA,
                             const int* __restrict__ offR, const int* __restrict__ eR,
                             const float* __restrict__ dvR, const uint4* __restrict__ hB,
                             const float* __restrict__ biasB,
                             float* __restrict__ outAB, int n,
                             float* __restrict__ stA, float* __restrict__ stB) {
    __shared__ float shSA[24], shQA[24], shSB[24], shQB[24];
    if (threadIdx.x < 24) {
        shSA[threadIdx.x] = 0.0f; shQA[threadIdx.x] = 0.0f;
        shSB[threadIdx.x] = 0.0f; shQB[threadIdx.x] = 0.0f;
    }
    __syncthreads();
    long long half = (long long)n * 3;
    long long t = (long long)blockIdx.x * blockDim.x + threadIdx.x;
    bool rev = (t >= half);
    long long lt = rev ? t - half : t;
    int node = (int)(lt / 3);
    int g = (int)(lt % 3);
    if (node < n) {
        const int* off = rev ? offR : offF;
        const int* edge = rev ? eR : eF;
        const uint4* h = rev ? hB : hA;
        const float* bias = rev ? biasB : biasA;
        const float* dinv = rev ? dvR : dvF;
        float f[8];
        {
            uint4 u = h[(size_t)node * 3 + g];
            float2 a = unpack2(u.x), b = unpack2(u.y), c = unpack2(u.z), d = unpack2(u.w);
            f[0] = a.x; f[1] = a.y; f[2] = b.x; f[3] = b.y;
            f[4] = c.x; f[5] = c.y; f[6] = d.x; f[7] = d.y;
        }
        int beg = node ? off[node - 1] : 0;
        int end = off[node];
        for (int j = beg; j < end; j++) {
            uint4 u = h[(size_t)edge[j] * 3 + g];
            float2 a = unpack2(u.x), b = unpack2(u.y), c = unpack2(u.z), d = unpack2(u.w);
            f[0] += a.x; f[1] += a.y; f[2] += b.x; f[3] += b.y;
            f[4] += c.x; f[5] += c.y; f[6] += d.x; f[7] += d.y;
        }
        float dv = dinv[node];
        float o[8];
#pragma unroll
        for (int k = 0; k < 8; k++) o[k] = dv * f[k] + bias[g * 8 + k];
        float* base = outAB + (size_t)node * 48 + (rev ? 24 : 0) + g * 8;
        float4 w0, w1;
        w0.x = o[0]; w0.y = o[1]; w0.z = o[2]; w0.w = o[3];
        w1.x = o[4]; w1.y = o[5]; w1.z = o[6]; w1.w = o[7];
        ((float4*)base)[0] = w0;
        ((float4*)base)[1] = w1;
        float* sS = rev ? shSB : shSA;
        float* sQ = rev ? shQB : shQA;
#pragma unroll
        for (int k = 0; k < 8; k++) {
            atomicAdd(&sS[g * 8 + k], o[k]);
            atomicAdd(&sQ[g * 8 + k], o[k] * o[k]);
        }
    }
    __syncthreads();
    if (threadIdx.x < 24) {
        float vS = shSA[threadIdx.x], vQ = shQA[threadIdx.x];
        if (vS != 0.0f || vQ != 0.0f) {
            atomicAdd(&stA[threadIdx.x], vS);
            atomicAdd(&stA[32 + threadIdx.x], vQ);
        }
        vS = shSB[threadIdx.x]; vQ = shQB[threadIdx.x];
        if (vS != 0.0f || vQ != 0.0f) {
            atomicAdd(&stB[threadIdx.x], vS);
            atomicAdd(&stB[32 + threadIdx.x], vQ);
        }
    }
}

// ---------------- fused head: inline affine + combine + even*odd + dot -----
__global__ void k_final(const int* __restrict__ idx, const float* __restrict__ AB,
                        const float* __restrict__ stA, const float* __restrict__ stB, int n,
                        const float* __restrict__ wA, const float* __restrict__ bA,
                        const float* __restrict__ aA, const float* __restrict__ wB,
                        const float* __restrict__ bB, const float* __restrict__ aB,
                        const float* __restrict__ pw, const float* __restrict__ pb,
                        float* __restrict__ out, int M) {
    __shared__ float sSA[24], sTA[24], sSB[24], sTB[24], sPw[24];
    if (threadIdx.x < 24) {
        int c = threadIdx.x;
        float invn = 1.0f / n;
        float avA = aA[c];
        float mA = stA[c] * invn;
        float vA = stA[32 + c] * invn - mA * mA * avA * (2.0f - avA);
        float sA = wA[c] * rsqrtf(vA + EPSV);
        sSA[c] = sA;
        sTA[c] = bA[c] - sA * avA * mA;
        float avB = aB[c];
        float mB = stB[c] * invn;
        float vB = stB[32 + c] * invn - mB * mB * avB * (2.0f - avB);
        float sB = wB[c] * rsqrtf(vB + EPSV);
        sSB[c] = sB;
        sTB[c] = bB[c] - sB * avB * mB;
        sPw[c] = pw[c];
    }
    __syncthreads();
    long long t = (long long)blockIdx.x * blockDim.x + threadIdx.x;
    int m = (int)(t >> 5);
    int lane = (int)(t & 31);
    if (m >= M) return;
    int ia = idx[2 * m], ib = idx[2 * m + 1];
    float v = 0.0f;
    if (lane < 24) {
        int c = lane;
        const float* ra = AB + (size_t)ia * 48;
        const float* rb = AB + (size_t)ib * 48;
        float xa = fmaxf(sSA[c] * ra[c] + sTA[c], 0.0f) +
                   fmaxf(sSB[c] * ra[24 + c] + sTB[c], 0.0f);
        float xb = fmaxf(sSA[c] * rb[c] + sTA[c], 0.0f) +
                   fmaxf(sSB[c] * rb[24 + c] + sTB[c], 0.0f);
        v = xa * xb * sPw[c];
    }
#pragma unroll
    for (int o = 16; o > 0; o >>= 1) v += __shfl_down_sync(0xffffffffu, v, o);
    if (lane == 0) out[m] = v + pb[0];
}

// ---------------------------------------------------------------------------
extern "C" void kernel_launch(void* const* d_in, const int* in_sizes, int n_in,
                              void* d_out, int out_size) {
    const int* x_ids = (const int*)d_in[0];
    const int* edge1 = (const int*)d_in[1];
    const int* pos   = (const int*)d_in[2];
    const int* ei2   = (const int*)d_in[3];
    const int* idx   = (const int*)d_in[4];
    const float* emb = (const float*)d_in[5];
    const float *gn0w = (const float*)d_in[6], *gn0b = (const float*)d_in[7], *gn0a = (const float*)d_in[8];
    const float *c1w0 = (const float*)d_in[9], *c1b0 = (const float*)d_in[10];
    const float *gn1w0 = (const float*)d_in[11], *gn1b0 = (const float*)d_in[12], *gn1a0 = (const float*)d_in[13];
    const float *c1w1 = (const float*)d_in[14], *c1b1 = (const float*)d_in[15];
    const float *gn1w1 = (const float*)d_in[16], *gn1b1 = (const float*)d_in[17], *gn1a1 = (const float*)d_in[18];
    const float *c2w = (const float*)d_in[19], *c2b = (const float*)d_in[20];
    const float *gn2w = (const float*)d_in[21], *gn2b = (const float*)d_in[22], *gn2a = (const float*)d_in[23];
    const float *c2rw = (const float*)d_in[24], *c2rb = (const float*)d_in[25];
    const float *gn2rw = (const float*)d_in[26], *gn2rb = (const float*)d_in[27], *gn2ra = (const float*)d_in[28];
    const float *pw = (const float*)d_in[29], *pb = (const float*)d_in[30];

    const int N  = in_sizes[0];
    const int E1 = in_sizes[1] / 2;
    const int P  = in_sizes[2] / 2;
    const int E2 = in_sizes[3] / 2;
    const int M  = P / 2;

    float *node0, *node1, *node2, *pairAB;
    uint4 *pairHa, *pairHb;
    float *dinv1, *dinv2f, *dinv2r, *statsf;
    int *cnt1, *off1, *cnt2f, *off2f, *cnt2r, *off2r, *aux, *e1, *e2f, *e2r;
    cudaGetSymbolAddress((void**)&node0, g_node0);
    cudaGetSymbolAddress((void**)&node1, g_node1);
    cudaGetSymbolAddress((void**)&node2, g_node2);
    cudaGetSymbolAddress((void**)&pairHa, g_pairHa);
    cudaGetSymbolAddress((void**)&pairHb, g_pairHb);
    cudaGetSymbolAddress((void**)&pairAB, g_pairAB);
    cudaGetSymbolAddress((void**)&dinv1, g_dinv1);
    cudaGetSymbolAddress((void**)&dinv2f, g_dinv2f);
    cudaGetSymbolAddress((void**)&dinv2r, g_dinv2r);
    cudaGetSymbolAddress((void**)&cnt1, g_cnt1);
    cudaGetSymbolAddress((void**)&off1, g_off1);
    cudaGetSymbolAddress((void**)&cnt2f, g_cnt2f);
    cudaGetSymbolAddress((void**)&off2f, g_off2f);
    cudaGetSymbolAddress((void**)&cnt2r, g_cnt2r);
    cudaGetSymbolAddress((void**)&off2r, g_off2r);
    cudaGetSymbolAddress((void**)&aux, g_aux);
    cudaGetSymbolAddress((void**)&e1, g_e1);
    cudaGetSymbolAddress((void**)&e2f, g_e2f);
    cudaGetSymbolAddress((void**)&e2r, g_e2r);
    cudaGetSymbolAddress((void**)&statsf, g_statsf);

    const int B = 256;
    const int nb1 = (N + 1023) / 1024;
    const int nb2 = (P + 1023) / 1024;
    const int nbe1 = (N + 255) / 256;
    const int nbe2 = (P + 255) / 256;
    const int Emax = (E1 > E2) ? E1 : E2;

    // build phase
    k_zero<<<GRID(P, B), B>>>(cnt1, cnt2f, cnt2r, statsf, N, P);
    k_cnt_all<<<GRID(Emax, B), B>>>(edge1, E1, ei2, E2, cnt1, cnt2f, cnt2r);
    k_scan1_all<<<nb1 + 2 * nb2, 1024>>>(cnt1, N, cnt2f, cnt2r, P, off1, off2f, off2r,
                                         aux, nb1, nb2);
    k_scan2_all<<<3, 1024>>>(aux, nb1, nb2);
    k_scan3_all<<<nbe1 + 2 * nbe2, 256>>>(off1, cnt1, dinv1, N, off2f, cnt2f, dinv2f,
                                          off2r, cnt2r, dinv2r, P, aux, nbe1, nbe2);
    k_fill_all<<<GRID(Emax, B), B>>>(edge1, E1, ei2, E2, off1, off2f, off2r, e1, e2f, e2r);

    // embedding + GN0 stats (flat)
    k_embed_stats<<<GRID((long long)N * 8, B), B>>>(x_ids, emb, node0, N, statsf + 0);

    // conv1 layer0
    k_mm<32, 32, 0><<<GRID(N, B), B>>>(node0, c1w0, dinv1, node1, N, statsf + 0, gn0w, gn0b, gn0a);
    k_gather_st<32><<<GRID((long long)N * 8, B), B>>>(off1, e1, dinv1, (const float4*)node1,
                                                      c1b0, (float4*)node2, N, statsf + 64);

    // conv1 layer1
    k_mm<32, 24, 1><<<GRID(N, B), B>>>(node2, c1w1, dinv1, node0, N, statsf + 64, gn1w0, gn1b0, gn1a0);
    k_gather_st<24><<<GRID((long long)N * 6, 192), 192>>>(off1, e1, dinv1, (const float4*)node0,
                                                          c1b1, (float4*)node1, N, statsf + 128);

    // pair features + dual 24x24 GEMM (fp16 messages, dinv folded)
    k_pair_mm<<<GRID(P, 128), 128>>>(pos, node1, N, statsf + 128, gn1w1, gn1b1, gn1a1,
                                     c2w, c2rw, dinv2f, dinv2r, pairHa, pairHb, P);

    // dual conv2 gather (fwd|rev halves) -> interleaved AB + fused stats
    k_gather_h2x<<<GRID(2LL * P * 3, 192), 192>>>(off2f, e2f, dinv2f, pairHa, c2b,
                                                  off2r, e2r, dinv2r, pairHb, c2rb,
                                                  pairAB, P, statsf + 192, statsf + 256);

    // fused head (inline affine)
    k_final<<<GRID((long long)M * 32, B), B>>>(idx, pairAB, statsf + 192, statsf + 256, P,
                                               gn2w, gn2b, gn2a, gn2rw, gn2rb, gn2ra,
                                               pw, pb, (float*)d_out, M);
}

// round 8
// speedup vs baseline: 1.4976x; 1.4976x over previous
#include <cuda_runtime.h>
#include <cuda_fp16.h>

// ---------------------------------------------------------------------------
// LocalWLNet round 8: round-5 (801us) structure + interleaved AB output from
// conv2 gathers + single 48-wide stats pass. 19 launches.
// ---------------------------------------------------------------------------

#define MAXN   100000
#define MAXP   1000000
#define MAXE1  3200000
#define MAXE2  4000000
#define EPSV   1e-5f

__device__ float g_node0[MAXN * 32];
__device__ float g_node1[MAXN * 32];
__device__ float g_node2[MAXN * 32];
__device__ uint4 g_pairHa[MAXP * 3];   // fp16: 24 halfs = 3 x uint4 per row
__device__ uint4 g_pairHb[MAXP * 3];
__device__ float g_pairAB[(size_t)MAXP * 48];  // interleaved [A24|B24]

__device__ int   g_cnt1[MAXN],  g_off1[MAXN];
__device__ int   g_cnt2f[MAXP], g_off2f[MAXP];
__device__ int   g_cnt2r[MAXP], g_off2r[MAXP];
__device__ float g_dinv1[MAXN], g_dinv2f[MAXP], g_dinv2r[MAXP];
__device__ int   g_e1[MAXE1];
__device__ int   g_e2f[MAXE2];
__device__ int   g_e2r[MAXE2];
__device__ int   g_aux[3072];
__device__ float g_statsf[5 * 64];   // per slot: [0:32) sum, [32:64) sumsq

static inline int GRID(long long n, int b) { return (int)((n + b - 1) / b); }

__device__ inline unsigned pack2(float a, float b) {
    __half2 h = __floats2half2_rn(a, b);
    return *reinterpret_cast<unsigned*>(&h);
}
__device__ inline float2 unpack2(unsigned u) {
    __half2 h = *reinterpret_cast<__half2*>(&u);
    return __half22float2(h);
}

// ---------------- zero accumulators ----------------
__global__ void k_zero(int* c1, int* c2f, int* c2r, float* st, int N, int P) {
    int i = blockIdx.x * blockDim.x + threadIdx.x;
    if (i < P) { c2f[i] = 0; c2r[i] = 0; }
    if (i < N) c1[i] = 0;
    if (i < 5 * 64) st[i] = 0.0f;
}

// ---------------- all three degree counts, one pass ----------------
__global__ void k_cnt_all(const int* __restrict__ edge1, int E1,
                          const int* __restrict__ ei2, int E2,
                          int* __restrict__ c1, int* __restrict__ c2f, int* __restrict__ c2r) {
    int i = blockIdx.x * blockDim.x + threadIdx.x;
    if (i < E1) atomicAdd(&c1[edge1[E1 + i]], 1);
    if (i < E2) {
        atomicAdd(&c2f[ei2[E2 + i]], 1);  // fwd dst = ei2[1]
        atomicAdd(&c2r[ei2[i]], 1);       // rev dst = ei2[0]
    }
}

// ---------------- sectioned exclusive scan ----------------
__global__ void k_scan1_all(const int* __restrict__ c1, int N,
                            const int* __restrict__ c2f, const int* __restrict__ c2r, int P,
                            int* __restrict__ o1, int* __restrict__ o2f, int* __restrict__ o2r,
                            int* __restrict__ aux, int nb1, int nb2) {
    const int* src; int* dst; int n, lb, ao;
    int b = blockIdx.x;
    if (b < nb1)            { src = c1;  dst = o1;  n = N; lb = b;             ao = 0; }
    else if (b < nb1 + nb2) { src = c2f; dst = o2f; n = P; lb = b - nb1;       ao = 1024; }
    else                    { src = c2r; dst = o2r; n = P; lb = b - nb1 - nb2; ao = 2048; }
    __shared__ int sh[1024];
    int i = lb * 1024 + threadIdx.x;
    int v = (i < n) ? src[i] : 0;
    sh[threadIdx.x] = v;
    __syncthreads();
    for (int o = 1; o < 1024; o <<= 1) {
        int t = (threadIdx.x >= o) ? sh[threadIdx.x - o] : 0;
        __syncthreads();
        sh[threadIdx.x] += t;
        __syncthreads();
    }
    if (i < n) dst[i] = sh[threadIdx.x] - v;  // exclusive within block
    if (threadIdx.x == 1023) aux[ao + lb] = sh[1023];
}

__global__ void k_scan2_all(int* __restrict__ aux, int nb1, int nb2) {
    int ao = blockIdx.x * 1024;
    int nb = (blockIdx.x == 0) ? nb1 : nb2;
    __shared__ int sh[1024];
    int v = (threadIdx.x < nb) ? aux[ao + threadIdx.x] : 0;
    sh[threadIdx.x] = v;
    __syncthreads();
    for (int o = 1; o < 1024; o <<= 1) {
        int t = (threadIdx.x >= o) ? sh[threadIdx.x - o] : 0;
        __syncthreads();
        sh[threadIdx.x] += t;
        __syncthreads();
    }
    if (threadIdx.x < nb) aux[ao + threadIdx.x] = sh[threadIdx.x] - v;  // exclusive
}

// scan3 + dinv
__global__ void k_scan3_all(int* __restrict__ o1, const int* __restrict__ c1,
                            float* __restrict__ dv1, int N,
                            int* __restrict__ o2f, const int* __restrict__ c2f,
                            float* __restrict__ dv2f,
                            int* __restrict__ o2r, const int* __restrict__ c2r,
                            float* __restrict__ dv2r, int P,
                            const int* __restrict__ aux, int nbe1, int nbe2) {
    int b = blockIdx.x;
    int* off; const int* cnt; float* dv; int n, lb, ao;
    if (b < nbe1)             { off = o1;  cnt = c1;  dv = dv1;  n = N; lb = b;               ao = 0; }
    else if (b < nbe1 + nbe2) { off = o2f; cnt = c2f; dv = dv2f; n = P; lb = b - nbe1;        ao = 1024; }
    else                      { off = o2r; cnt = c2r; dv = dv2r; n = P; lb = b - nbe1 - nbe2; ao = 2048; }
    int i = lb * 256 + threadIdx.x;
    if (i < n) {
        off[i] += aux[ao + (i >> 10)];
        dv[i] = rsqrtf((float)cnt[i] + 1.0f);
    }
}

// ---------------- fill all CSRs (off doubles as cursor) ----------------
__global__ void k_fill_all(const int* __restrict__ edge1, int E1,
                           const int* __restrict__ ei2, int E2,
                           int* __restrict__ o1, int* __restrict__ o2f, int* __restrict__ o2r,
                           int* __restrict__ e1, int* __restrict__ e2f, int* __restrict__ e2r) {
    int i = blockIdx.x * blockDim.x + threadIdx.x;
    if (i < E1) {
        int s = edge1[i], d = edge1[E1 + i];
        e1[atomicAdd(&o1[d], 1)] = s;
    }
    if (i < E2) {
        int s = ei2[i], d = ei2[E2 + i];
        e2f[atomicAdd(&o2f[d], 1)] = s;
        e2r[atomicAdd(&o2r[s], 1)] = d;
    }
}

// ---------------- embedding gather ----------------
__global__ void k_embed(const int* __restrict__ ids, const float* __restrict__ emb,
                        float* __restrict__ out, int n) {
    int t = blockIdx.x * blockDim.x + threadIdx.x;
    if (t >= n * 8) return;
    int r = t >> 3, g = t & 7;
    float4 v = *(const float4*)(emb + (size_t)ids[r] * 32 + g * 4);
    *(float4*)(out + (size_t)r * 32 + g * 4) = v;
}

// ---------------- float stats: per-column sum & sumsq ----------------
template <int C>
__global__ void k_statsf(const float4* __restrict__ x4, int n, float* st) {
    constexpr int G = C / 4;
    int g = threadIdx.x;   // < G
    int ty = threadIdx.y;  // < 64
    float4 s = {0, 0, 0, 0}, q = {0, 0, 0, 0};
    for (int r = blockIdx.x * 64 + ty; r < n; r += gridDim.x * 64) {
        float4 v = x4[(size_t)r * G + g];
        s.x += v.x; s.y += v.y; s.z += v.z; s.w += v.w;
        q.x += v.x * v.x; q.y += v.y * v.y; q.z += v.z * v.z; q.w += v.w * v.w;
    }
    __shared__ float4 shS[64][8], shQ[64][8];
    shS[ty][g] = s;
    shQ[ty][g] = q;
    __syncthreads();
    if (ty == 0) {
        for (int t = 1; t < 64; t++) {
            float4 a = shS[t][g], b = shQ[t][g];
            s.x += a.x; s.y += a.y; s.z += a.z; s.w += a.w;
            q.x += b.x; q.y += b.y; q.z += b.z; q.w += b.w;
        }
        atomicAdd(&st[g * 4 + 0], s.x); atomicAdd(&st[g * 4 + 1], s.y);
        atomicAdd(&st[g * 4 + 2], s.z); atomicAdd(&st[g * 4 + 3], s.w);
        atomicAdd(&st[32 + g * 4 + 0], q.x); atomicAdd(&st[32 + g * 4 + 1], q.y);
        atomicAdd(&st[32 + g * 4 + 2], q.z); atomicAdd(&st[32 + g * 4 + 3], q.w);
    }
}

// ---------------- 48-wide stats over interleaved AB: both slots, one pass --
__global__ void k_stats48(const float4* __restrict__ x4, int n,
                          float* __restrict__ stA, float* __restrict__ stB) {
    int g = threadIdx.x;   // < 12
    int ty = threadIdx.y;  // < 32
    float4 s = {0, 0, 0, 0}, q = {0, 0, 0, 0};
    for (int r = blockIdx.x * 32 + ty; r < n; r += gridDim.x * 32) {
        float4 v = x4[(size_t)r * 12 + g];
        s.x += v.x; s.y += v.y; s.z += v.z; s.w += v.w;
        q.x += v.x * v.x; q.y += v.y * v.y; q.z += v.z * v.z; q.w += v.w * v.w;
    }
    __shared__ float4 shS[32][12], shQ[32][12];
    shS[ty][g] = s;
    shQ[ty][g] = q;
    __syncthreads();
    if (ty == 0) {
        for (int t = 1; t < 32; t++) {
            float4 a = shS[t][g], b = shQ[t][g];
            s.x += a.x; s.y += a.y; s.z += a.z; s.w += a.w;
            q.x += b.x; q.y += b.y; q.z += b.z; q.w += b.w;
        }
        float* st = (g < 6) ? stA : stB;
        int gg = (g < 6) ? g : g - 6;
        atomicAdd(&st[gg * 4 + 0], s.x); atomicAdd(&st[gg * 4 + 1], s.y);
        atomicAdd(&st[gg * 4 + 2], s.z); atomicAdd(&st[gg * 4 + 3], s.w);
        atomicAdd(&st[32 + gg * 4 + 0], q.x); atomicAdd(&st[32 + gg * 4 + 1], q.y);
        atomicAdd(&st[32 + gg * 4 + 2], q.z); atomicAdd(&st[32 + gg * 4 + 3], q.w);
    }
}

// ---------------- h' = dinv * (norm(x) @ W) ----------------
template <int CIN, int COUT, int RELU>
__global__ void k_mm(const float* __restrict__ x, const float* __restrict__ W,
                     const float* __restrict__ dinv, float* __restrict__ h, int n,
                     const float* __restrict__ st, const float* __restrict__ gw,
                     const float* __restrict__ gb, const float* __restrict__ ga) {
    __shared__ float Ws[CIN * COUT];
    __shared__ float S[CIN], T[CIN];
    for (int t = threadIdx.x; t < CIN * COUT; t += blockDim.x) Ws[t] = W[t];
    if (threadIdx.x < CIN) {
        int c = threadIdx.x;
        double av = (double)ga[c];
        double m = (double)st[c] / n;
        double var = (double)st[32 + c] / n - m * m * av * (2.0 - av);
        float s = gw[c] * rsqrtf((float)var + EPSV);
        S[c] = s;
        T[c] = gb[c] - (float)((double)s * av * m);
    }
    __syncthreads();
    int i = blockIdx.x * blockDim.x + threadIdx.x;
    if (i >= n) return;
    float acc[COUT];
#pragma unroll
    for (int j = 0; j < COUT; j++) acc[j] = 0.0f;
    const float* xr = x + (size_t)i * CIN;
#pragma unroll
    for (int k = 0; k < CIN; k++) {
        float xv = S[k] * xr[k] + T[k];
        if (RELU) xv = fmaxf(xv, 0.0f);
#pragma unroll
        for (int j = 0; j < COUT; j++) acc[j] += xv * Ws[k * COUT + j];
    }
    float dv = dinv[i];
    float* hr = h + (size_t)i * COUT;
#pragma unroll
    for (int j = 0; j < COUT; j++) hr[j] = dv * acc[j];
}

// ---------------- fp32 CSR gather (flat, one (node,g) per thread) ----------
template <int C>
__global__ void k_gather(const int* __restrict__ off, const int* __restrict__ edge,
                         const float* __restrict__ dinv, const float4* __restrict__ h4,
                         const float* __restrict__ bias, float4* __restrict__ out, int n) {
    constexpr int G = C / 4;
    long long t = (long long)blockIdx.x * blockDim.x + threadIdx.x;
    int node = (int)(t / G);
    int g = (int)(t % G);
    if (node >= n) return;
    float4 sum = h4[(size_t)node * G + g];
    int beg = node ? off[node - 1] : 0;  // off[d] = end after fill
    int end = off[node];
    for (int j = beg; j < end; j++) {
        int s = edge[j];
        float4 v = h4[(size_t)s * G + g];
        sum.x += v.x; sum.y += v.y; sum.z += v.z; sum.w += v.w;
    }
    float dv = dinv[node];
    float4 acc;
    acc.x = dv * sum.x + bias[g * 4 + 0];
    acc.y = dv * sum.y + bias[g * 4 + 1];
    acc.z = dv * sum.z + bias[g * 4 + 2];
    acc.w = dv * sum.w + bias[g * 4 + 3];
    out[(size_t)node * G + g] = acc;
}

// ---------------- pair: xp = norm(x[a])*norm(x[b]); dual GEMM; fp16 out ----
__global__ void k_pair_mm(const int* __restrict__ pos, const float* __restrict__ xn,
                          int nNode, const float* __restrict__ st,
                          const float* __restrict__ gw, const float* __restrict__ gb,
                          const float* __restrict__ ga, const float* __restrict__ W1,
                          const float* __restrict__ W2, const float* __restrict__ dvf,
                          const float* __restrict__ dvr, uint4* __restrict__ ha,
                          uint4* __restrict__ hb, int P) {
    __shared__ float Ws1[24 * 24], Ws2[24 * 24], S[24], T[24];
    for (int t = threadIdx.x; t < 24 * 24; t += blockDim.x) {
        Ws1[t] = W1[t];
        Ws2[t] = W2[t];
    }
    if (threadIdx.x < 24) {
        int c = threadIdx.x;
        double av = (double)ga[c];
        double m = (double)st[c] / nNode;
        double var = (double)st[32 + c] / nNode - m * m * av * (2.0 - av);
        float s = gw[c] * rsqrtf((float)var + EPSV);
        S[c] = s;
        T[c] = gb[c] - (float)((double)s * av * m);
    }
    __syncthreads();
    int p = blockIdx.x * blockDim.x + threadIdx.x;
    if (p >= P) return;
    int ia = pos[2 * p], ib = pos[2 * p + 1];
    const float4* x4 = (const float4*)xn;
    float x[24];
#pragma unroll
    for (int q = 0; q < 6; q++) {
        float4 va = x4[(size_t)ia * 6 + q];
        float4 vb = x4[(size_t)ib * 6 + q];
        int c = q * 4;
        x[c + 0] = (S[c + 0] * va.x + T[c + 0]) * (S[c + 0] * vb.x + T[c + 0]);
        x[c + 1] = (S[c + 1] * va.y + T[c + 1]) * (S[c + 1] * vb.y + T[c + 1]);
        x[c + 2] = (S[c + 2] * va.z + T[c + 2]) * (S[c + 2] * vb.z + T[c + 2]);
        x[c + 3] = (S[c + 3] * va.w + T[c + 3]) * (S[c + 3] * vb.w + T[c + 3]);
    }
    float a1[24], a2[24];
#pragma unroll
    for (int j = 0; j < 24; j++) { a1[j] = 0.0f; a2[j] = 0.0f; }
#pragma unroll
    for (int k = 0; k < 24; k++) {
        float xv = x[k];
#pragma unroll
        for (int j = 0; j < 24; j++) {
            a1[j] += xv * Ws1[k * 24 + j];
            a2[j] += xv * Ws2[k * 24 + j];
        }
    }
    float df = dvf[p], dr = dvr[p];
    uint4 u;
    u.x = pack2(df * a1[0], df * a1[1]);   u.y = pack2(df * a1[2], df * a1[3]);
    u.z = pack2(df * a1[4], df * a1[5]);   u.w = pack2(df * a1[6], df * a1[7]);
    ha[(size_t)p * 3 + 0] = u;
    u.x = pack2(df * a1[8], df * a1[9]);   u.y = pack2(df * a1[10], df * a1[11]);
    u.z = pack2(df * a1[12], df * a1[13]); u.w = pack2(df * a1[14], df * a1[15]);
    ha[(size_t)p * 3 + 1] = u;
    u.x = pack2(df * a1[16], df * a1[17]); u.y = pack2(df * a1[18], df * a1[19]);
    u.z = pack2(df * a1[20], df * a1[21]); u.w = pack2(df * a1[22], df * a1[23]);
    ha[(size_t)p * 3 + 2] = u;
    u.x = pack2(dr * a2[0], dr * a2[1]);   u.y = pack2(dr * a2[2], dr * a2[3]);
    u.z = pack2(dr * a2[4], dr * a2[5]);   u.w = pack2(dr * a2[6], dr * a2[7]);
    hb[(size_t)p * 3 + 0] = u;
    u.x = pack2(dr * a2[8], dr * a2[9]);   u.y = pack2(dr * a2[10], dr * a2[11]);
    u.z = pack2(dr * a2[12], dr * a2[13]); u.w = pack2(dr * a2[14], dr * a2[15]);
    hb[(size_t)p * 3 + 1] = u;
    u.x = pack2(dr * a2[16], dr * a2[17]); u.y = pack2(dr * a2[18], dr * a2[19]);
    u.z = pack2(dr * a2[20], dr * a2[21]); u.w = pack2(dr * a2[22], dr * a2[23]);
    hb[(size_t)p * 3 + 2] = u;
}

// ---------------- fp16 CSR gather (flat) -> interleaved AB slot ------------
// OFS = 0 (A slot) or 24 (B slot); output row stride = 48 floats.
template <int OFS>
__global__ void k_gather_h(const int* __restrict__ off, const int* __restrict__ edge,
                           const float* __restrict__ dinv, const uint4* __restrict__ h,
                           const float* __restrict__ bias, float* __restrict__ outAB, int n) {
    long long t = (long long)blockIdx.x * blockDim.x + threadIdx.x;
    int node = (int)(t / 3);
    int g = (int)(t % 3);
    if (node >= n) return;
    float f[8];
    {
        uint4 u = h[(size_t)node * 3 + g];
        float2 a = unpack2(u.x), b = unpack2(u.y), c = unpack2(u.z), d = unpack2(u.w);
        f[0] = a.x; f[1] = a.y; f[2] = b.x; f[3] = b.y;
        f[4] = c.x; f[5] = c.y; f[6] = d.x; f[7] = d.y;
    }
    int beg = node ? off[node - 1] : 0;
    int end = off[node];
    for (int j = beg; j < end; j++) {
        int s = edge[j];
        uint4 u = h[(size_t)s * 3 + g];
        float2 a = unpack2(u.x), b = unpack2(u.y), c = unpack2(u.z), d = unpack2(u.w);
        f[0] += a.x; f[1] += a.y; f[2] += b.x; f[3] += b.y;
        f[4] += c.x; f[5] += c.y; f[6] += d.x; f[7] += d.y;
    }
    float dv = dinv[node];
    const float* bs = bias + g * 8;
    float4 o0, o1;
    o0.x = dv * f[0] + bs[0]; o0.y = dv * f[1] + bs[1];
    o0.z = dv * f[2] + bs[2]; o0.w = dv * f[3] + bs[3];
    o1.x = dv * f[4] + bs[4]; o1.y = dv * f[5] + bs[5];
    o1.z = dv * f[6] + bs[6]; o1.w = dv * f[7] + bs[7];
    float* base = outAB + (size_t)node * 48 + OFS + g * 8;
    ((float4*)base)[0] = o0;
    ((float4*)base)[1] = o1;
}

// ---------------- fused head: inline affine + combine + even*odd + dot -----
__global__ void k_final(const int* __restrict__ idx, const float* __restrict__ AB,
                        const float* __restrict__ stA, const float* __restrict__ stB, int n,
                        const float* __restrict__ wA, const float* __restrict__ bA,
                        const float* __restrict__ aA, const float* __restrict__ wB,
                        const float* __restrict__ bB, const float* __restrict__ aB,
                        const float* __restrict__ pw, const float* __restrict__ pb,
                        float* __restrict__ out, int M) {
    __shared__ float sSA[24], sTA[24], sSB[24], sTB[24], sPw[24];
    if (threadIdx.x < 24) {
        int c = threadIdx.x;
        float invn = 1.0f / n;
        float avA = aA[c];
        float mA = stA[c] * invn;
        float vA = stA[32 + c] * invn - mA * mA * avA * (2.0f - avA);
        float sA = wA[c] * rsqrtf(vA + EPSV);
        sSA[c] = sA;
        sTA[c] = bA[c] - sA * avA * mA;
        float avB = aB[c];
        float mB = stB[c] * invn;
        float vB = stB[32 + c] * invn - mB * mB * avB * (2.0f - avB);
        float sB = wB[c] * rsqrtf(vB + EPSV);
        sSB[c] = sB;
        sTB[c] = bB[c] - sB * avB * mB;
        sPw[c] = pw[c];
    }
    __syncthreads();
    long long t = (long long)blockIdx.x * blockDim.x + threadIdx.x;
    int m = (int)(t >> 5);
    int lane = (int)(t & 31);
    if (m >= M) return;
    int ia = idx[2 * m], ib = idx[2 * m + 1];
    float v = 0.0f;
    if (lane < 24) {
        int c = lane;
        const float* ra = AB + (size_t)ia * 48;
        const float* rb = AB + (size_t)ib * 48;
        float xa = fmaxf(sSA[c] * ra[c] + sTA[c], 0.0f) +
                   fmaxf(sSB[c] * ra[24 + c] + sTB[c], 0.0f);
        float xb = fmaxf(sSA[c] * rb[c] + sTA[c], 0.0f) +
                   fmaxf(sSB[c] * rb[24 + c] + sTB[c], 0.0f);
        v = xa * xb * sPw[c];
    }
#pragma unroll
    for (int o = 16; o > 0; o >>= 1) v += __shfl_down_sync(0xffffffffu, v, o);
    if (lane == 0) out[m] = v + pb[0];
}

// ---------------------------------------------------------------------------
extern "C" void kernel_launch(void* const* d_in, const int* in_sizes, int n_in,
                              void* d_out, int out_size) {
    const int* x_ids = (const int*)d_in[0];
    const int* edge1 = (const int*)d_in[1];
    const int* pos   = (const int*)d_in[2];
    const int* ei2   = (const int*)d_in[3];
    const int* idx   = (const int*)d_in[4];
    const float* emb = (const float*)d_in[5];
    const float *gn0w = (const float*)d_in[6], *gn0b = (const float*)d_in[7], *gn0a = (const float*)d_in[8];
    const float *c1w0 = (const float*)d_in[9], *c1b0 = (const float*)d_in[10];
    const float *gn1w0 = (const float*)d_in[11], *gn1b0 = (const float*)d_in[12], *gn1a0 = (const float*)d_in[13];
    const float *c1w1 = (const float*)d_in[14], *c1b1 = (const float*)d_in[15];
    const float *gn1w1 = (const float*)d_in[16], *gn1b1 = (const float*)d_in[17], *gn1a1 = (const float*)d_in[18];
    const float *c2w = (const float*)d_in[19], *c2b = (const float*)d_in[20];
    const float *gn2w = (const float*)d_in[21], *gn2b = (const float*)d_in[22], *gn2a = (const float*)d_in[23];
    const float *c2rw = (const float*)d_in[24], *c2rb = (const float*)d_in[25];
    const float *gn2rw = (const float*)d_in[26], *gn2rb = (const float*)d_in[27], *gn2ra = (const float*)d_in[28];
    const float *pw = (const float*)d_in[29], *pb = (const float*)d_in[30];

    const int N  = in_sizes[0];
    const int E1 = in_sizes[1] / 2;
    const int P  = in_sizes[2] / 2;
    const int E2 = in_sizes[3] / 2;
    const int M  = P / 2;

    float *node0, *node1, *node2, *pairAB;
    uint4 *pairHa, *pairHb;
    float *dinv1, *dinv2f, *dinv2r, *statsf;
    int *cnt1, *off1, *cnt2f, *off2f, *cnt2r, *off2r, *aux, *e1, *e2f, *e2r;
    cudaGetSymbolAddress((void**)&node0, g_node0);
    cudaGetSymbolAddress((void**)&node1, g_node1);
    cudaGetSymbolAddress((void**)&node2, g_node2);
    cudaGetSymbolAddress((void**)&pairHa, g_pairHa);
    cudaGetSymbolAddress((void**)&pairHb, g_pairHb);
    cudaGetSymbolAddress((void**)&pairAB, g_pairAB);
    cudaGetSymbolAddress((void**)&dinv1, g_dinv1);
    cudaGetSymbolAddress((void**)&dinv2f, g_dinv2f);
    cudaGetSymbolAddress((void**)&dinv2r, g_dinv2r);
    cudaGetSymbolAddress((void**)&cnt1, g_cnt1);
    cudaGetSymbolAddress((void**)&off1, g_off1);
    cudaGetSymbolAddress((void**)&cnt2f, g_cnt2f);
    cudaGetSymbolAddress((void**)&off2f, g_off2f);
    cudaGetSymbolAddress((void**)&cnt2r, g_cnt2r);
    cudaGetSymbolAddress((void**)&off2r, g_off2r);
    cudaGetSymbolAddress((void**)&aux, g_aux);
    cudaGetSymbolAddress((void**)&e1, g_e1);
    cudaGetSymbolAddress((void**)&e2f, g_e2f);
    cudaGetSymbolAddress((void**)&e2r, g_e2r);
    cudaGetSymbolAddress((void**)&statsf, g_statsf);

    const int B = 256;
    const int nb1 = (N + 1023) / 1024;
    const int nb2 = (P + 1023) / 1024;
    const int nbe1 = (N + 255) / 256;
    const int nbe2 = (P + 255) / 256;
    const int Emax = (E1 > E2) ? E1 : E2;

    // build phase (6 launches)
    k_zero<<<GRID(P, B), B>>>(cnt1, cnt2f, cnt2r, statsf, N, P);
    k_cnt_all<<<GRID(Emax, B), B>>>(edge1, E1, ei2, E2, cnt1, cnt2f, cnt2r);
    k_scan1_all<<<nb1 + 2 * nb2, 1024>>>(cnt1, N, cnt2f, cnt2r, P, off1, off2f, off2r,
                                         aux, nb1, nb2);
    k_scan2_all<<<3, 1024>>>(aux, nb1, nb2);
    k_scan3_all<<<nbe1 + 2 * nbe2, 256>>>(off1, cnt1, dinv1, N, off2f, cnt2f, dinv2f,
                                          off2r, cnt2r, dinv2r, P, aux, nbe1, nbe2);
    k_fill_all<<<GRID(Emax, B), B>>>(edge1, E1, ei2, E2, off1, off2f, off2r, e1, e2f, e2r);

    // embedding + GN0 stats
    k_embed<<<GRID((long long)N * 8, B), B>>>(x_ids, emb, node0, N);
    k_statsf<32><<<256, dim3(8, 64)>>>((const float4*)node0, N, statsf + 0);

    // conv1 layer0
    k_mm<32, 32, 0><<<GRID(N, B), B>>>(node0, c1w0, dinv1, node1, N, statsf + 0, gn0w, gn0b, gn0a);
    k_gather<32><<<GRID((long long)N * 8, B), B>>>(off1, e1, dinv1, (const float4*)node1, c1b0,
                                                   (float4*)node2, N);
    k_statsf<32><<<256, dim3(8, 64)>>>((const float4*)node2, N, statsf + 64);

    // conv1 layer1
    k_mm<32, 24, 1><<<GRID(N, B), B>>>(node2, c1w1, dinv1, node0, N, statsf + 64, gn1w0, gn1b0, gn1a0);
    k_gather<24><<<GRID((long long)N * 6, B), B>>>(off1, e1, dinv1, (const float4*)node0, c1b1,
                                                   (float4*)node1, N);
    k_statsf<24><<<256, dim3(6, 64)>>>((const float4*)node1, N, statsf + 128);

    // pair features + dual 24x24 GEMM (fp16 messages, dinv folded)
    k_pair_mm<<<GRID(P, 128), 128>>>(pos, node1, N, statsf + 128, gn1w1, gn1b1, gn1a1,
                                     c2w, c2rw, dinv2f, dinv2r, pairHa, pairHb, P);

    // conv2 fwd / rev gathers -> interleaved AB slots
    k_gather_h<0><<<GRID((long long)P * 3, B), B>>>(off2f, e2f, dinv2f, pairHa, c2b, pairAB, P);
    k_gather_h<24><<<GRID((long long)P * 3, B), B>>>(off2r, e2r, dinv2r, pairHb, c2rb, pairAB, P);

    // one 48-wide stats pass over AB (both slots)
    k_stats48<<<1024, dim3(12, 32)>>>((const float4*)pairAB, P, statsf + 192, statsf + 256);

    // fused head (inline affine)
    k_final<<<GRID((long long)M * 32, B), B>>>(idx, pairAB, statsf + 192, statsf + 256, P,
                                               gn2w, gn2b, gn2a, gn2rw, gn2rb, gn2ra,
                                               pw, pb, (float*)d_out, M);
}

// round 10
// speedup vs baseline: 1.5427x; 1.0301x over previous
#include <cuda_runtime.h>
#include <cuda_fp16.h>

// ---------------------------------------------------------------------------
// LocalWLNet round 9: round-5 (801us) compute kernels + CSR build overlapped
// on a second stream (event fork/join, graph-capturable).
// ---------------------------------------------------------------------------

#define MAXN   100000
#define MAXP   1000000
#define MAXE1  3200000
#define MAXE2  4000000
#define EPSV   1e-5f

__device__ float g_node0[MAXN * 32];
__device__ float g_node1[MAXN * 32];
__device__ float g_node2[MAXN * 32];
__device__ uint4 g_pairHa[MAXP * 3];   // fp16: 24 halfs = 3 x uint4 per row
__device__ uint4 g_pairHb[MAXP * 3];
__device__ float g_pairA[MAXP * 24];
__device__ float g_pairB[MAXP * 24];

__device__ int   g_cnt1[MAXN],  g_off1[MAXN];
__device__ int   g_cnt2f[MAXP], g_off2f[MAXP];
__device__ int   g_cnt2r[MAXP], g_off2r[MAXP];
__device__ float g_dinv1[MAXN], g_dinv2f[MAXP], g_dinv2r[MAXP];
__device__ int   g_e1[MAXE1];
__device__ int   g_e2f[MAXE2];
__device__ int   g_e2r[MAXE2];
__device__ int   g_aux[3072];
__device__ float g_statsf[5 * 64];   // per slot: [0:32) sum, [32:64) sumsq

static inline int GRID(long long n, int b) { return (int)((n + b - 1) / b); }

__device__ inline unsigned pack2(float a, float b) {
    __half2 h = __floats2half2_rn(a, b);
    return *reinterpret_cast<unsigned*>(&h);
}
__device__ inline float2 unpack2(unsigned u) {
    __half2 h = *reinterpret_cast<__half2*>(&u);
    return __half22float2(h);
}

// ---------------- zero accumulators ----------------
__global__ void k_zero(int* c1, int* c2f, int* c2r, float* st, int N, int P) {
    int i = blockIdx.x * blockDim.x + threadIdx.x;
    if (i < P) { c2f[i] = 0; c2r[i] = 0; }
    if (i < N) c1[i] = 0;
    if (i < 5 * 64) st[i] = 0.0f;
}

// ---------------- degree counts ----------------
__global__ void k_cnt1(const int* __restrict__ dst, int E, int* __restrict__ c1) {
    int i = blockIdx.x * blockDim.x + threadIdx.x;
    if (i < E) atomicAdd(&c1[dst[i]], 1);
}

__global__ void k_cnt2(const int* __restrict__ ei2, int E2,
                       int* __restrict__ c2f, int* __restrict__ c2r) {
    int i = blockIdx.x * blockDim.x + threadIdx.x;
    if (i < E2) {
        atomicAdd(&c2f[ei2[E2 + i]], 1);  // fwd dst = ei2[1]
        atomicAdd(&c2r[ei2[i]], 1);       // rev dst = ei2[0]
    }
}

// ---------------- graph1 scan (single array) ----------------
__global__ void k_scanA1(const int* __restrict__ cnt, int n, int* __restrict__ off,
                         int* __restrict__ aux) {
    __shared__ int sh[1024];
    int i = blockIdx.x * 1024 + threadIdx.x;
    int v = (i < n) ? cnt[i] : 0;
    sh[threadIdx.x] = v;
    __syncthreads();
    for (int o = 1; o < 1024; o <<= 1) {
        int t = (threadIdx.x >= o) ? sh[threadIdx.x - o] : 0;
        __syncthreads();
        sh[threadIdx.x] += t;
        __syncthreads();
    }
    if (i < n) off[i] = sh[threadIdx.x] - v;
    if (threadIdx.x == 1023) aux[blockIdx.x] = sh[1023];
}

__global__ void k_scanA2(int* __restrict__ aux, int nb) {
    __shared__ int sh[1024];
    int v = (threadIdx.x < nb) ? aux[threadIdx.x] : 0;
    sh[threadIdx.x] = v;
    __syncthreads();
    for (int o = 1; o < 1024; o <<= 1) {
        int t = (threadIdx.x >= o) ? sh[threadIdx.x - o] : 0;
        __syncthreads();
        sh[threadIdx.x] += t;
        __syncthreads();
    }
    if (threadIdx.x < nb) aux[threadIdx.x] = sh[threadIdx.x] - v;
}

__global__ void k_scanA3(int* __restrict__ off, const int* __restrict__ cnt,
                         float* __restrict__ dv, int n, const int* __restrict__ aux) {
    int i = blockIdx.x * blockDim.x + threadIdx.x;
    if (i < n) {
        off[i] += aux[i >> 10];
        dv[i] = rsqrtf((float)cnt[i] + 1.0f);
    }
}

__global__ void k_fill1(const int* __restrict__ edge1, int E1,
                        int* __restrict__ o1, int* __restrict__ e1) {
    int i = blockIdx.x * blockDim.x + threadIdx.x;
    if (i < E1) {
        int s = edge1[i], d = edge1[E1 + i];
        e1[atomicAdd(&o1[d], 1)] = s;
    }
}

// ---------------- graph2 scan (two arrays, sectioned) ----------------
__global__ void k_scanB1(const int* __restrict__ cf, const int* __restrict__ cr, int P,
                         int* __restrict__ of, int* __restrict__ orr,
                         int* __restrict__ aux, int nb2) {
    const int* src; int* dst; int lb, ao;
    int b = blockIdx.x;
    if (b < nb2) { src = cf; dst = of;  lb = b;       ao = 0; }
    else         { src = cr; dst = orr; lb = b - nb2; ao = 1024; }
    __shared__ int sh[1024];
    int i = lb * 1024 + threadIdx.x;
    int v = (i < P) ? src[i] : 0;
    sh[threadIdx.x] = v;
    __syncthreads();
    for (int o = 1; o < 1024; o <<= 1) {
        int t = (threadIdx.x >= o) ? sh[threadIdx.x - o] : 0;
        __syncthreads();
        sh[threadIdx.x] += t;
        __syncthreads();
    }
    if (i < P) dst[i] = sh[threadIdx.x] - v;
    if (threadIdx.x == 1023) aux[ao + lb] = sh[1023];
}

__global__ void k_scanB2(int* __restrict__ aux, int nb) {
    int ao = blockIdx.x * 1024;
    __shared__ int sh[1024];
    int v = (threadIdx.x < nb) ? aux[ao + threadIdx.x] : 0;
    sh[threadIdx.x] = v;
    __syncthreads();
    for (int o = 1; o < 1024; o <<= 1) {
        int t = (threadIdx.x >= o) ? sh[threadIdx.x - o] : 0;
        __syncthreads();
        sh[threadIdx.x] += t;
        __syncthreads();
    }
    if (threadIdx.x < nb) aux[ao + threadIdx.x] = sh[threadIdx.x] - v;
}

__global__ void k_scanB3(int* __restrict__ of, const int* __restrict__ cf,
                         float* __restrict__ dvf,
                         int* __restrict__ orr, const int* __restrict__ cr,
                         float* __restrict__ dvr, int P,
                         const int* __restrict__ aux, int nbe) {
    int b = blockIdx.x;
    int* off; const int* cnt; float* dv; int lb, ao;
    if (b < nbe) { off = of;  cnt = cf; dv = dvf; lb = b;       ao = 0; }
    else         { off = orr; cnt = cr; dv = dvr; lb = b - nbe; ao = 1024; }
    int i = lb * 256 + threadIdx.x;
    if (i < P) {
        off[i] += aux[ao + (i >> 10)];
        dv[i] = rsqrtf((float)cnt[i] + 1.0f);
    }
}

__global__ void k_fill2(const int* __restrict__ ei2, int E2,
                        int* __restrict__ o2f, int* __restrict__ o2r,
                        int* __restrict__ e2f, int* __restrict__ e2r) {
    int i = blockIdx.x * blockDim.x + threadIdx.x;
    if (i < E2) {
        int s = ei2[i], d = ei2[E2 + i];
        e2f[atomicAdd(&o2f[d], 1)] = s;
        e2r[atomicAdd(&o2r[s], 1)] = d;
    }
}

// ---------------- embedding gather ----------------
__global__ void k_embed(const int* __restrict__ ids, const float* __restrict__ emb,
                        float* __restrict__ out, int n) {
    int t = blockIdx.x * blockDim.x + threadIdx.x;
    if (t >= n * 8) return;
    int r = t >> 3, g = t & 7;
    float4 v = *(const float4*)(emb + (size_t)ids[r] * 32 + g * 4);
    *(float4*)(out + (size_t)r * 32 + g * 4) = v;
}

// ---------------- float stats: per-column sum & sumsq ----------------
template <int C>
__global__ void k_statsf(const float4* __restrict__ x4, int n, float* st) {
    constexpr int G = C / 4;
    int g = threadIdx.x;   // < G
    int ty = threadIdx.y;  // < 64
    float4 s = {0, 0, 0, 0}, q = {0, 0, 0, 0};
    for (int r = blockIdx.x * 64 + ty; r < n; r += gridDim.x * 64) {
        float4 v = x4[(size_t)r * G + g];
        s.x += v.x; s.y += v.y; s.z += v.z; s.w += v.w;
        q.x += v.x * v.x; q.y += v.y * v.y; q.z += v.z * v.z; q.w += v.w * v.w;
    }
    __shared__ float4 shS[64][8], shQ[64][8];
    shS[ty][g] = s;
    shQ[ty][g] = q;
    __syncthreads();
    if (ty == 0) {
        for (int t = 1; t < 64; t++) {
            float4 a = shS[t][g], b = shQ[t][g];
            s.x += a.x; s.y += a.y; s.z += a.z; s.w += a.w;
            q.x += b.x; q.y += b.y; q.z += b.z; q.w += b.w;
        }
        atomicAdd(&st[g * 4 + 0], s.x); atomicAdd(&st[g * 4 + 1], s.y);
        atomicAdd(&st[g * 4 + 2], s.z); atomicAdd(&st[g * 4 + 3], s.w);
        atomicAdd(&st[32 + g * 4 + 0], q.x); atomicAdd(&st[32 + g * 4 + 1], q.y);
        atomicAdd(&st[32 + g * 4 + 2], q.z); atomicAdd(&st[32 + g * 4 + 3], q.w);
    }
}

// ---------------- h' = dinv * (norm(x) @ W) ----------------
template <int CIN, int COUT, int RELU>
__global__ void k_mm(const float* __restrict__ x, const float* __restrict__ W,
                     const float* __restrict__ dinv, float* __restrict__ h, int n,
                     const float* __restrict__ st, const float* __restrict__ gw,
                     const float* __restrict__ gb, const float* __restrict__ ga) {
    __shared__ float Ws[CIN * COUT];
    __shared__ float S[CIN], T[CIN];
    for (int t = threadIdx.x; t < CIN * COUT; t += blockDim.x) Ws[t] = W[t];
    if (threadIdx.x < CIN) {
        int c = threadIdx.x;
        double av = (double)ga[c];
        double m = (double)st[c] / n;
        double var = (double)st[32 + c] / n - m * m * av * (2.0 - av);
        float s = gw[c] * rsqrtf((float)var + EPSV);
        S[c] = s;
        T[c] = gb[c] - (float)((double)s * av * m);
    }
    __syncthreads();
    int i = blockIdx.x * blockDim.x + threadIdx.x;
    if (i >= n) return;
    float acc[COUT];
#pragma unroll
    for (int j = 0; j < COUT; j++) acc[j] = 0.0f;
    const float* xr = x + (size_t)i * CIN;
#pragma unroll
    for (int k = 0; k < CIN; k++) {
        float xv = S[k] * xr[k] + T[k];
        if (RELU) xv = fmaxf(xv, 0.0f);
#pragma unroll
        for (int j = 0; j < COUT; j++) acc[j] += xv * Ws[k * COUT + j];
    }
    float dv = dinv[i];
    float* hr = h + (size_t)i * COUT;
#pragma unroll
    for (int j = 0; j < COUT; j++) hr[j] = dv * acc[j];
}

// ---------------- fp32 CSR gather (flat, one (node,g) per thread) ----------
template <int C>
__global__ void k_gather(const int* __restrict__ off, const int* __restrict__ edge,
                         const float* __restrict__ dinv, const float4* __restrict__ h4,
                         const float* __restrict__ bias, float4* __restrict__ out, int n) {
    constexpr int G = C / 4;
    long long t = (long long)blockIdx.x * blockDim.x + threadIdx.x;
    int node = (int)(t / G);
    int g = (int)(t % G);
    if (node >= n) return;
    float4 sum = h4[(size_t)node * G + g];
    int beg = node ? off[node - 1] : 0;  // off[d] = end after fill
    int end = off[node];
    for (int j = beg; j < end; j++) {
        int s = edge[j];
        float4 v = h4[(size_t)s * G + g];
        sum.x += v.x; sum.y += v.y; sum.z += v.z; sum.w += v.w;
    }
    float dv = dinv[node];
    float4 acc;
    acc.x = dv * sum.x + bias[g * 4 + 0];
    acc.y = dv * sum.y + bias[g * 4 + 1];
    acc.z = dv * sum.z + bias[g * 4 + 2];
    acc.w = dv * sum.w + bias[g * 4 + 3];
    out[(size_t)node * G + g] = acc;
}

// ---------------- pair: xp = norm(x[a])*norm(x[b]); dual GEMM; fp16 out ----
__global__ void k_pair_mm(const int* __restrict__ pos, const float* __restrict__ xn,
                          int nNode, const float* __restrict__ st,
                          const float* __restrict__ gw, const float* __restrict__ gb,
                          const float* __restrict__ ga, const float* __restrict__ W1,
                          const float* __restrict__ W2, const float* __restrict__ dvf,
                          const float* __restrict__ dvr, uint4* __restrict__ ha,
                          uint4* __restrict__ hb, int P) {
    __shared__ float Ws1[24 * 24], Ws2[24 * 24], S[24], T[24];
    for (int t = threadIdx.x; t < 24 * 24; t += blockDim.x) {
        Ws1[t] = W1[t];
        Ws2[t] = W2[t];
    }
    if (threadIdx.x < 24) {
        int c = threadIdx.x;
        double av = (double)ga[c];
        double m = (double)st[c] / nNode;
        double var = (double)st[32 + c] / nNode - m * m * av * (2.0 - av);
        float s = gw[c] * rsqrtf((float)var + EPSV);
        S[c] = s;
        T[c] = gb[c] - (float)((double)s * av * m);
    }
    __syncthreads();
    int p = blockIdx.x * blockDim.x + threadIdx.x;
    if (p >= P) return;
    int ia = pos[2 * p], ib = pos[2 * p + 1];
    const float4* x4 = (const float4*)xn;
    float x[24];
#pragma unroll
    for (int q = 0; q < 6; q++) {
        float4 va = x4[(size_t)ia * 6 + q];
        float4 vb = x4[(size_t)ib * 6 + q];
        int c = q * 4;
        x[c + 0] = (S[c + 0] * va.x + T[c + 0]) * (S[c + 0] * vb.x + T[c + 0]);
        x[c + 1] = (S[c + 1] * va.y + T[c + 1]) * (S[c + 1] * vb.y + T[c + 1]);
        x[c + 2] = (S[c + 2] * va.z + T[c + 2]) * (S[c + 2] * vb.z + T[c + 2]);
        x[c + 3] = (S[c + 3] * va.w + T[c + 3]) * (S[c + 3] * vb.w + T[c + 3]);
    }
    float a1[24], a2[24];
#pragma unroll
    for (int j = 0; j < 24; j++) { a1[j] = 0.0f; a2[j] = 0.0f; }
#pragma unroll
    for (int k = 0; k < 24; k++) {
        float xv = x[k];
#pragma unroll
        for (int j = 0; j < 24; j++) {
            a1[j] += xv * Ws1[k * 24 + j];
            a2[j] += xv * Ws2[k * 24 + j];
        }
    }
    float df = dvf[p], dr = dvr[p];
    uint4 u;
    u.x = pack2(df * a1[0], df * a1[1]);   u.y = pack2(df * a1[2], df * a1[3]);
    u.z = pack2(df * a1[4], df * a1[5]);   u.w = pack2(df * a1[6], df * a1[7]);
    ha[(size_t)p * 3 + 0] = u;
    u.x = pack2(df * a1[8], df * a1[9]);   u.y = pack2(df * a1[10], df * a1[11]);
    u.z = pack2(df * a1[12], df * a1[13]); u.w = pack2(df * a1[14], df * a1[15]);
    ha[(size_t)p * 3 + 1] = u;
    u.x = pack2(df * a1[16], df * a1[17]); u.y = pack2(df * a1[18], df * a1[19]);
    u.z = pack2(df * a1[20], df * a1[21]); u.w = pack2(df * a1[22], df * a1[23]);
    ha[(size_t)p * 3 + 2] = u;
    u.x = pack2(dr * a2[0], dr * a2[1]);   u.y = pack2(dr * a2[2], dr * a2[3]);
    u.z = pack2(dr * a2[4], dr * a2[5]);   u.w = pack2(dr * a2[6], dr * a2[7]);
    hb[(size_t)p * 3 + 0] = u;
    u.x = pack2(dr * a2[8], dr * a2[9]);   u.y = pack2(dr * a2[10], dr * a2[11]);
    u.z = pack2(dr * a2[12], dr * a2[13]); u.w = pack2(dr * a2[14], dr * a2[15]);
    hb[(size_t)p * 3 + 1] = u;
    u.x = pack2(dr * a2[16], dr * a2[17]); u.y = pack2(dr * a2[18], dr * a2[19]);
    u.z = pack2(dr * a2[20], dr * a2[21]); u.w = pack2(dr * a2[22], dr * a2[23]);
    hb[(size_t)p * 3 + 2] = u;
}

// ---------------- fp16 CSR gather (flat): 3 groups x 8 halfs ----------------
__global__ void k_gather_h(const int* __restrict__ off, const int* __restrict__ edge,
                           const float* __restrict__ dinv, const uint4* __restrict__ h,
                           const float* __restrict__ bias, float4* __restrict__ out, int n) {
    long long t = (long long)blockIdx.x * blockDim.x + threadIdx.x;
    int node = (int)(t / 3);
    int g = (int)(t % 3);
    if (node >= n) return;
    float f[8];
    {
        uint4 u = h[(size_t)node * 3 + g];
        float2 a = unpack2(u.x), b = unpack2(u.y), c = unpack2(u.z), d = unpack2(u.w);
        f[0] = a.x; f[1] = a.y; f[2] = b.x; f[3] = b.y;
        f[4] = c.x; f[5] = c.y; f[6] = d.x; f[7] = d.y;
    }
    int beg = node ? off[node - 1] : 0;
    int end = off[node];
    for (int j = beg; j < end; j++) {
        int s = edge[j];
        uint4 u = h[(size_t)s * 3 + g];
        float2 a = unpack2(u.x), b = unpack2(u.y), c = unpack2(u.z), d = unpack2(u.w);
        f[0] += a.x; f[1] += a.y; f[2] += b.x; f[3] += b.y;
        f[4] += c.x; f[5] += c.y; f[6] += d.x; f[7] += d.y;
    }
    float dv = dinv[node];
    const float* bs = bias + g * 8;
    float4 o0, o1;
    o0.x = dv * f[0] + bs[0]; o0.y = dv * f[1] + bs[1];
    o0.z = dv * f[2] + bs[2]; o0.w = dv * f[3] + bs[3];
    o1.x = dv * f[4] + bs[4]; o1.y = dv * f[5] + bs[5];
    o1.z = dv * f[6] + bs[6]; o1.w = dv * f[7] + bs[7];
    out[(size_t)node * 6 + g * 2 + 0] = o0;
    out[(size_t)node * 6 + g * 2 + 1] = o1;
}

// ---------------- fused head: inline affine + combine + even*odd + dot -----
__global__ void k_final(const int* __restrict__ idx, const float* __restrict__ A,
                        const float* __restrict__ B,
                        const float* __restrict__ stA, const float* __restrict__ stB, int n,
                        const float* __restrict__ wA, const float* __restrict__ bA,
                        const float* __restrict__ aA, const float* __restrict__ wB,
                        const float* __restrict__ bB, const float* __restrict__ aB,
                        const float* __restrict__ pw, const float* __restrict__ pb,
                        float* __restrict__ out, int M) {
    __shared__ float sSA[24], sTA[24], sSB[24], sTB[24], sPw[24];
    if (threadIdx.x < 24) {
        int c = threadIdx.x;
        float invn = 1.0f / n;
        float avA = aA[c];
        float mA = stA[c] * invn;
        float vA = stA[32 + c] * invn - mA * mA * avA * (2.0f - avA);
        float sA = wA[c] * rsqrtf(vA + EPSV);
        sSA[c] = sA;
        sTA[c] = bA[c] - sA * avA * mA;
        float avB = aB[c];
        float mB = stB[c] * invn;
        float vB = stB[32 + c] * invn - mB * mB * avB * (2.0f - avB);
        float sB = wB[c] * rsqrtf(vB + EPSV);
        sSB[c] = sB;
        sTB[c] = bB[c] - sB * avB * mB;
        sPw[c] = pw[c];
    }
    __syncthreads();
    long long t = (long long)blockIdx.x * blockDim.x + threadIdx.x;
    int m = (int)(t >> 5);
    int lane = (int)(t & 31);
    if (m >= M) return;
    int ia = idx[2 * m], ib = idx[2 * m + 1];
    float v = 0.0f;
    if (lane < 24) {
        int c = lane;
        float xa = fmaxf(sSA[c] * A[(size_t)ia * 24 + c] + sTA[c], 0.0f) +
                   fmaxf(sSB[c] * B[(size_t)ia * 24 + c] + sTB[c], 0.0f);
        float xb = fmaxf(sSA[c] * A[(size_t)ib * 24 + c] + sTA[c], 0.0f) +
                   fmaxf(sSB[c] * B[(size_t)ib * 24 + c] + sTB[c], 0.0f);
        v = xa * xb * sPw[c];
    }
#pragma unroll
    for (int o = 16; o > 0; o >>= 1) v += __shfl_down_sync(0xffffffffu, v, o);
    if (lane == 0) out[m] = v + pb[0];
}

// ---------------------------------------------------------------------------
extern "C" void kernel_launch(void* const* d_in, const int* in_sizes, int n_in,
                              void* d_out, int out_size) {
    const int* x_ids = (const int*)d_in[0];
    const int* edge1 = (const int*)d_in[1];
    const int* pos   = (const int*)d_in[2];
    const int* ei2   = (const int*)d_in[3];
    const int* idx   = (const int*)d_in[4];
    const float* emb = (const float*)d_in[5];
    const float *gn0w = (const float*)d_in[6], *gn0b = (const float*)d_in[7], *gn0a = (const float*)d_in[8];
    const float *c1w0 = (const float*)d_in[9], *c1b0 = (const float*)d_in[10];
    const float *gn1w0 = (const float*)d_in[11], *gn1b0 = (const float*)d_in[12], *gn1a0 = (const float*)d_in[13];
    const float *c1w1 = (const float*)d_in[14], *c1b1 = (const float*)d_in[15];
    const float *gn1w1 = (const float*)d_in[16], *gn1b1 = (const float*)d_in[17], *gn1a1 = (const float*)d_in[18];
    const float *c2w = (const float*)d_in[19], *c2b = (const float*)d_in[20];
    const float *gn2w = (const float*)d_in[21], *gn2b = (const float*)d_in[22], *gn2a = (const float*)d_in[23];
    const float *c2rw = (const float*)d_in[24], *c2rb = (const float*)d_in[25];
    const float *gn2rw = (const float*)d_in[26], *gn2rb = (const float*)d_in[27], *gn2ra = (const float*)d_in[28];
    const float *pw = (const float*)d_in[29], *pb = (const float*)d_in[30];

    const int N  = in_sizes[0];
    const int E1 = in_sizes[1] / 2;
    const int P  = in_sizes[2] / 2;
    const int E2 = in_sizes[3] / 2;
    const int M  = P / 2;

    float *node0, *node1, *node2, *pairA, *pairB;
    uint4 *pairHa, *pairHb;
    float *dinv1, *dinv2f, *dinv2r, *statsf;
    int *cnt1, *off1, *cnt2f, *off2f, *cnt2r, *off2r, *aux, *e1, *e2f, *e2r;
    cudaGetSymbolAddress((void**)&node0, g_node0);
    cudaGetSymbolAddress((void**)&node1, g_node1);
    cudaGetSymbolAddress((void**)&node2, g_node2);
    cudaGetSymbolAddress((void**)&pairHa, g_pairHa);
    cudaGetSymbolAddress((void**)&pairHb, g_pairHb);
    cudaGetSymbolAddress((void**)&pairA, g_pairA);
    cudaGetSymbolAddress((void**)&pairB, g_pairB);
    cudaGetSymbolAddress((void**)&dinv1, g_dinv1);
    cudaGetSymbolAddress((void**)&dinv2f, g_dinv2f);
    cudaGetSymbolAddress((void**)&dinv2r, g_dinv2r);
    cudaGetSymbolAddress((void**)&cnt1, g_cnt1);
    cudaGetSymbolAddress((void**)&off1, g_off1);
    cudaGetSymbolAddress((void**)&cnt2f, g_cnt2f);
    cudaGetSymbolAddress((void**)&off2f, g_off2f);
    cudaGetSymbolAddress((void**)&cnt2r, g_cnt2r);
    cudaGetSymbolAddress((void**)&off2r, g_off2r);
    cudaGetSymbolAddress((void**)&aux, g_aux);
    cudaGetSymbolAddress((void**)&e1, g_e1);
    cudaGetSymbolAddress((void**)&e2f, g_e2f);
    cudaGetSymbolAddress((void**)&e2r, g_e2r);
    cudaGetSymbolAddress((void**)&statsf, g_statsf);

    // lazy-once stream/events (host objects, no device memory)
    static cudaStream_t s2 = nullptr;
    static cudaEvent_t evF = nullptr, evJ1 = nullptr, evJ2 = nullptr;
    if (s2 == nullptr) {
        cudaStreamCreateWithFlags(&s2, cudaStreamNonBlocking);
        cudaEventCreateWithFlags(&evF, cudaEventDisableTiming);
        cudaEventCreateWithFlags(&evJ1, cudaEventDisableTiming);
        cudaEventCreateWithFlags(&evJ2, cudaEventDisableTiming);
    }

    const int B = 256;
    const int nb1 = (N + 1023) / 1024;
    const int nb2 = (P + 1023) / 1024;
    const int nbe2 = (P + 255) / 256;

    // stream 0: zero, then fork
    k_zero<<<GRID(P, B), B>>>(cnt1, cnt2f, cnt2r, statsf, N, P);
    cudaEventRecord(evF, 0);
    cudaStreamWaitEvent(s2, evF, 0);

    // s2: graph1 build
    k_cnt1<<<GRID(E1, B), B, 0, s2>>>(edge1 + E1, E1, cnt1);
    k_scanA1<<<nb1, 1024, 0, s2>>>(cnt1, N, off1, aux);
    k_scanA2<<<1, 1024, 0, s2>>>(aux, nb1);
    k_scanA3<<<GRID(N, B), B, 0, s2>>>(off1, cnt1, dinv1, N, aux);
    k_fill1<<<GRID(E1, B), B, 0, s2>>>(edge1, E1, off1, e1);
    cudaEventRecord(evJ1, s2);

    // s2: graph2 build
    k_cnt2<<<GRID(E2, B), B, 0, s2>>>(ei2, E2, cnt2f, cnt2r);
    k_scanB1<<<2 * nb2, 1024, 0, s2>>>(cnt2f, cnt2r, P, off2f, off2r, aux + 1024, nb2);
    k_scanB2<<<2, 1024, 0, s2>>>(aux + 1024, nb2);
    k_scanB3<<<2 * nbe2, 256, 0, s2>>>(off2f, cnt2f, dinv2f, off2r, cnt2r, dinv2r, P,
                                       aux + 1024, nbe2);
    k_fill2<<<GRID(E2, B), B, 0, s2>>>(ei2, E2, off2f, off2r, e2f, e2r);
    cudaEventRecord(evJ2, s2);

    // stream 0: embedding + GN0 stats (independent of builds)
    k_embed<<<GRID((long long)N * 8, B), B>>>(x_ids, emb, node0, N);
    k_statsf<32><<<256, dim3(8, 64)>>>((const float4*)node0, N, statsf + 0);

    // join graph1 before conv1 (mm needs dinv1, gather needs e1)
    cudaStreamWaitEvent(0, evJ1, 0);

    // conv1 layer0
    k_mm<32, 32, 0><<<GRID(N, B), B>>>(node0, c1w0, dinv1, node1, N, statsf + 0, gn0w, gn0b, gn0a);
    k_gather<32><<<GRID((long long)N * 8, B), B>>>(off1, e1, dinv1, (const float4*)node1, c1b0,
                                                   (float4*)node2, N);
    k_statsf<32><<<256, dim3(8, 64)>>>((const float4*)node2, N, statsf + 64);

    // conv1 layer1
    k_mm<32, 24, 1><<<GRID(N, B), B>>>(node2, c1w1, dinv1, node0, N, statsf + 64, gn1w0, gn1b0, gn1a0);
    k_gather<24><<<GRID((long long)N * 6, B), B>>>(off1, e1, dinv1, (const float4*)node0, c1b1,
                                                   (float4*)node1, N);
    k_statsf<24><<<256, dim3(6, 64)>>>((const float4*)node1, N, statsf + 128);

    // join graph2 before pair phase (needs dinv2f/r, then e2f/e2r)
    cudaStreamWaitEvent(0, evJ2, 0);

    // pair features + dual 24x24 GEMM (fp16 messages, dinv folded)
    k_pair_mm<<<GRID(P, 128), 128>>>(pos, node1, N, statsf + 128, gn1w1, gn1b1, gn1a1,
                                     c2w, c2rw, dinv2f, dinv2r, pairHa, pairHb, P);

    // conv2 fwd / rev gathers + stats
    k_gather_h<<<GRID((long long)P * 3, B), B>>>(off2f, e2f, dinv2f, pairHa, c2b,
                                                 (float4*)pairA, P);
    k_statsf<24><<<512, dim3(6, 64)>>>((const float4*)pairA, P, statsf + 192);
    k_gather_h<<<GRID((long long)P * 3, B), B>>>(off2r, e2r, dinv2r, pairHb, c2rb,
                                                 (float4*)pairB, P);
    k_statsf<24><<<512, dim3(6, 64)>>>((const float4*)pairB, P, statsf + 256);

    // fused head (inline affine)
    k_final<<<GRID((long long)M * 32, B), B>>>(idx, pairA, pairB, statsf + 192, statsf + 256, P,
                                               gn2w, gn2b, gn2a, gn2rw, gn2rb, gn2ra,
                                               pw, pb, (float*)d_out, M);
}